// round 15
// baseline (speedup 1.0000x reference)
#include <cuda_runtime.h>
#include <cuda_fp16.h>

// ---------------------------------------------------------------------------
// InterpolatingBSpline2d, round 10: 2-lane cooperative gather with
// bank-engineered row pitch.
//
// Measured: per-thread random gather has crossbar conflict factor f~3.2
// (L1 74.7% busy; bytes floor 7.5us -> ~24us of the 35.4). Per-thread
// layouts cannot reduce f. Fix: rows padded to 34 uint4 (bank-quad stride
// +2 per row), 2 lanes per point (lane h owns rows ix+2h, ix+2h+1), so a
// point's 8 chunks cover all 8 quads and each warp-instruction phase holds
// 4 points as {q_i, q_i+4} pairs -> f ~ 2.13. One shfl_xor round combines.
//
// Table: fp16 dual shifted-copy (copy1 = copy0 shifted one y-slot), row
// pitch 272 halfs (544B), copy = 35,904B, total smem 71,808B (3 blocks/SM).
//
// Prologue: in-place Thomas (R7-R9 proven), constants for the new pitch:
//   fp32 scratch slot U(c,jx,my) at float idx
//     (c&2 ? 8976 : 0) + jx*136 + 2*my + (c&1)
//   stage2 (t=4*jx+c, lockstep warp, volatile half stores) overwrites floats
//   with copy0 halfs at >=2-slot slack; copy1 built by shifted uint2 copy.
// ---------------------------------------------------------------------------

#define M_GRID   64
#define NP2      66
#define NINNER   62
#define NCH      4
#define ROW_F    136                      // floats per row (pitch) = 544 B
#define ROW_H    272                      // halfs per row
#define ROW_U4   34                       // uint4 per row (mod 8 == 2)
#define ROW_U2   68                       // uint2 (8B y-slots) per row
#define COPY_F   (NP2 * ROW_F)            // 8976 floats per copy region
#define COPY_H   (NP2 * ROW_H)            // 17952 halfs per copy
#define COPY_U4  (COPY_H / 8)             // 2244
#define COPY_U2  (COPY_H / 4)             // 4488
#define SMEM_BYTES (2 * COPY_H * 2)       // 71,808

// ---- compile-time Thomas factors ------------------------------------------
struct Fac { float cp[NINNER]; float invden[NINNER]; };

constexpr Fac make_fac() {
    Fac f{};
    const float B = 2.0f / 3.0f, A = 1.0f / 6.0f;
    float c = A / B;
    f.cp[0] = c;
    f.invden[0] = 1.0f / B;
    for (int m = 1; m < NINNER; ++m) {
        float den = B - A * c;
        float inv = 1.0f / den;
        c = A * inv;
        f.cp[m] = c;
        f.invden[m] = inv;
    }
    return f;
}
__constant__ Fac FAC = make_fac();

__device__ __forceinline__ unsigned short f2h(float v)
{
    return __half_as_ushort(__float2half_rn(v));
}

__device__ __forceinline__ float2 h2f(unsigned v)
{
    __half2 h = *reinterpret_cast<const __half2*>(&v);
    return __half22float2(h);
}

__global__ void __launch_bounds__(512, 3) bspline_fused(
    const float* __restrict__ data,
    const float2* __restrict__ u,
    float4* __restrict__ out, int n)
{
    extern __shared__ __align__(16) float sf[];     // 71,808 B
    __half* sh = reinterpret_cast<__half*>(sf);
    const int t = threadIdx.x;
    const float S = 1.0f / 6.0f;

    // ======== stage 1: solve along x (256 threads, one (c,my) chain) ========
    if (t < 256) {
        const int c  = t >> 6;
        const int my = t & 63;
        const float* src = data + c * (M_GRID * M_GRID) + my;   // stride 64
        float* B = sf + ((c & 2) ? COPY_F : 0) + 2 * my + (c & 1);

        float d0 = src[0];
        float a  = (src[64] - d0 * S) * FAC.invden[0];
        B[0] = a;                                   // dp[0]
#pragma unroll
        for (int m = 1; m <= 60; ++m) {
            a = (src[(m + 1) * 64] - a * S) * FAC.invden[m];
            B[m * ROW_F] = a;                       // dp[m]
        }
        float d63 = src[63 * 64];
        a = (src[62 * 64] - d63 * S - a * S) * FAC.invden[61];  // dp[61]

        float z = a;                                // x63
        B[65 * ROW_F] = 2.0f * d63 - z;
        B[64 * ROW_F] = d63;
        B[63 * ROW_F] = z;
#pragma unroll
        for (int m = 60; m >= 0; --m) {
            z = B[m * ROW_F] - FAC.cp[m] * z;       // read dp[m], emit x_{m+2}
            B[(m + 2) * ROW_F] = z;                 // slack-2, own-thread
        }
        B[ROW_F] = d0;                              // x1
        B[0]     = 2.0f * d0 - z;                   // x0 (z holds x2)
    }
    __syncthreads();

    // ======== stage 2: solve along y (264 threads, t = 4*jx + c) ========
    if (t < NCH * NP2) {
        const int jx = t >> 2, c = t & 3;
        const float* R = sf + ((c & 2) ? COPY_F : 0) + jx * ROW_F + (c & 1);
        float* W = const_cast<float*>(R);
        volatile unsigned short* T =
            reinterpret_cast<volatile unsigned short*>(sh);
        const int r0 = jx * ROW_H + c;              // copy0 half base, row jx

        float d0 = R[0];
        float carry = (R[2] - d0 * S) * FAC.invden[0];
        W[0] = carry;                               // dp[0]
#pragma unroll
        for (int m = 1; m <= 60; ++m) {
            carry = (R[(m + 1) * 2] - carry * S) * FAC.invden[m];
            W[m * 2] = carry;                       // dp[m]
        }
        float s62 = R[62 * 2], d63 = R[63 * 2];
        carry = (s62 - d63 * S - carry * S) * FAC.invden[61];   // dp[61]

        float z = carry;                            // x63
        T[r0 + 65 * 4] = f2h(2.0f * d63 - z);       // y=65
        T[r0 + 64 * 4] = f2h(d63);                  // y=64
        T[r0 + 63 * 4] = f2h(z);                    // y=63
#pragma unroll
        for (int m = 60; m >= 0; --m) {
            z = R[m * 2] - FAC.cp[m] * z;
            T[r0 + (m + 2) * 4] = f2h(z);           // clobbers dp[m+2]: slack 2
        }
        T[r0 + 4] = f2h(d0);                        // y=1
        T[r0]     = f2h(2.0f * d0 - z);             // y=0 (z holds x2)
    }
    __syncthreads();

    // ======== copy1: per row, slot y = copy0 slot y+1 (8B granules) ========
    {
        uint2* s64 = reinterpret_cast<uint2*>(sf);
        for (int k = t; k < NP2 * 65; k += blockDim.x) {
            int jx = k / 65;
            int y  = k - jx * 65;
            s64[COPY_U2 + jx * ROW_U2 + y] = s64[jx * ROW_U2 + y + 1];
        }
    }
    __syncthreads();

    // ======== gather: 2-lane cooperative, bank-engineered ========
    const int lane = t & 31;
    const int g    = lane >> 1;            // point slot 0..15 within warp
    const int h    = lane & 1;             // row-pair half
    const int wid  = (blockIdx.x * blockDim.x + t) >> 5;
    const int nw   = (gridDim.x * blockDim.x) >> 5;
    const uint4* S4 = reinterpret_cast<const uint4*>(sf);

    for (int base = wid * 16; base < n; base += nw * 16) {
        int p  = base + g;
        int pc = p < n ? p : n - 1;
        float2 P = u[pc];

        float uxn = P.x * 63.0f;
        float fx  = floorf(uxn);
        int   ix  = (int)fx;
        float tx  = uxn - fx;
        if (uxn < 0.0f)   { ix = 0;  tx = uxn; }
        if (uxn >= 62.0f) { ix = 62; tx = uxn - 62.0f; }

        float uyn = P.y * 63.0f;
        float fy  = floorf(uyn);
        int   iy  = (int)fy;
        float ty  = uyn - fy;
        if (uyn < 0.0f)   { iy = 0;  ty = uyn; }
        if (uyn >= 62.0f) { iy = 62; ty = uyn - 62.0f; }

        float wx0 = ((-S * tx + 0.5f) * tx - 0.5f) * tx + S;
        float wx1 = ((0.5f * tx - 1.0f) * tx) * tx + (2.0f / 3.0f);
        float wx2 = ((-0.5f * tx + 0.5f) * tx + 0.5f) * tx + S;
        float wx3 = (S * tx) * tx * tx;

        float wy0 = ((-S * ty + 0.5f) * ty - 0.5f) * ty + S;
        float wy1 = ((0.5f * ty - 1.0f) * ty) * ty + (2.0f / 3.0f);
        float wy2 = ((-0.5f * ty + 0.5f) * ty + 0.5f) * ty + S;
        float wy3 = (S * ty) * ty * ty;

        int iy2 = iy & ~1;
        int a   = (iy & 1) * COPY_U4 + (ix + 2 * h) * ROW_U4 + (iy2 >> 1);

        // row A = ix + 2h
        uint4 qa = S4[a], qb = S4[a + 1];
        float2 a01 = h2f(qa.x), a23 = h2f(qa.y);
        float2 b01 = h2f(qa.z), b23 = h2f(qa.w);
        float2 c01 = h2f(qb.x), c23 = h2f(qb.y);
        float2 d01 = h2f(qb.z), d23 = h2f(qb.w);
        float rA0 = a01.x * wy0 + b01.x * wy1 + c01.x * wy2 + d01.x * wy3;
        float rA1 = a01.y * wy0 + b01.y * wy1 + c01.y * wy2 + d01.y * wy3;
        float rA2 = a23.x * wy0 + b23.x * wy1 + c23.x * wy2 + d23.x * wy3;
        float rA3 = a23.y * wy0 + b23.y * wy1 + c23.y * wy2 + d23.y * wy3;

        // row B = ix + 2h + 1
        uint4 qc = S4[a + ROW_U4], qd = S4[a + ROW_U4 + 1];
        a01 = h2f(qc.x); a23 = h2f(qc.y);
        b01 = h2f(qc.z); b23 = h2f(qc.w);
        c01 = h2f(qd.x); c23 = h2f(qd.y);
        d01 = h2f(qd.z); d23 = h2f(qd.w);
        float rB0 = a01.x * wy0 + b01.x * wy1 + c01.x * wy2 + d01.x * wy3;
        float rB1 = a01.y * wy0 + b01.y * wy1 + c01.y * wy2 + d01.y * wy3;
        float rB2 = a23.x * wy0 + b23.x * wy1 + c23.x * wy2 + d23.x * wy3;
        float rB3 = a23.y * wy0 + b23.y * wy1 + c23.y * wy2 + d23.y * wy3;

        float wxa = h ? wx2 : wx0;
        float wxb = h ? wx3 : wx1;
        float v0 = wxa * rA0 + wxb * rB0;
        float v1 = wxa * rA1 + wxb * rB1;
        float v2 = wxa * rA2 + wxb * rB2;
        float v3 = wxa * rA3 + wxb * rB3;

        v0 += __shfl_xor_sync(0xffffffffu, v0, 1);
        v1 += __shfl_xor_sync(0xffffffffu, v1, 1);
        v2 += __shfl_xor_sync(0xffffffffu, v2, 1);
        v3 += __shfl_xor_sync(0xffffffffu, v3, 1);

        if (h == 0 && p < n)
            out[p] = make_float4(v0, v1, v2, v3);
    }
}

extern "C" void kernel_launch(void* const* d_in, const int* in_sizes, int n_in,
                              void* d_out, int out_size)
{
    const float2* u    = (const float2*)d_in[0];
    const float*  data = (const float*)d_in[1];
    int n = in_sizes[0] / 2;

    cudaFuncSetAttribute(bspline_fused,
                         cudaFuncAttributeMaxDynamicSharedMemorySize, SMEM_BYTES);

    bspline_fused<<<444, 512, SMEM_BYTES>>>(data, u, (float4*)d_out, n);
}